// round 2
// baseline (speedup 1.0000x reference)
#include <cuda_runtime.h>

#define BB 64
#define PP 32768
#define GG 64

// ---------------- device scratch (no allocations allowed) ----------------
__device__ float  g_bt_ov[BB * PP];     // best_truth_overlap per (b,p)
__device__ int    g_bt_idx[BB * PP];    // best_truth_idx per (b,p)
__device__ float  g_bp_ov[BB * GG];     // best_prior_overlap per (b,g)
__device__ int    g_bp_idx[BB * GG];    // best_prior_idx per (b,g)
__device__ float  g_lossc[BB * PP];     // loss_c for mining (0 at pos)
__device__ int    g_numpos[BB];
__device__ int    g_anyvalid[BB];
__device__ double g_accb[BB][3];        // 0: loss_l, 1: loss_landm, 2: loss_c over pos
__device__ double g_topk;               // sum of top-k loss_c over all batches

__device__ __forceinline__ float sl1(float d) {
    float a = fabsf(d);
    return a < 1.0f ? 0.5f * d * d : a - 0.5f;
}

// ---------------- init ----------------
__global__ void k_init() {
    int t = threadIdx.x;
    if (t < BB) {
        g_numpos[t] = 0;
        g_accb[t][0] = 0.0;
        g_accb[t][1] = 0.0;
        g_accb[t][2] = 0.0;
    }
    if (t == 0) g_topk = 0.0;
}

// ---------------- phase A: per-prior max/argmax over GTs ----------------
__global__ void __launch_bounds__(256) k_phaseA(const float* __restrict__ priors,
                                                const float* __restrict__ targets) {
    __shared__ float sx1[GG], sy1[GG], sx2[GG], sy2[GG], sar[GG];
    int b = blockIdx.y;
    int tid = threadIdx.x;
    const float* tb = targets + (size_t)b * GG * 15;
    for (int g = tid; g < GG; g += blockDim.x) {
        float x1 = tb[g * 15 + 0], y1 = tb[g * 15 + 1];
        float x2 = tb[g * 15 + 2], y2 = tb[g * 15 + 3];
        sx1[g] = x1; sy1[g] = y1; sx2[g] = x2; sy2[g] = y2;
        sar[g] = (x2 - x1) * (y2 - y1);
    }
    __syncthreads();

    int p = blockIdx.x * blockDim.x + tid;
    float4 pr = ((const float4*)priors)[p];
    float px1 = pr.x - pr.z * 0.5f, py1 = pr.y - pr.w * 0.5f;
    float px2 = pr.x + pr.z * 0.5f, py2 = pr.y + pr.w * 0.5f;
    float parea = (px2 - px1) * (py2 - py1);

    float b_in = -1.0f, b_un = 1.0f;  // sentinel ratio = -1, g=0 always wins
    int b_ix = 0;
#pragma unroll 8
    for (int g = 0; g < GG; g++) {
        float lx = fmaxf(sx1[g], px1), ly = fmaxf(sy1[g], py1);
        float rx = fminf(sx2[g], px2), ry = fminf(sy2[g], py2);
        float w = fmaxf(rx - lx, 0.0f), h = fmaxf(ry - ly, 0.0f);
        float inter = w * h;
        float un = sar[g] + parea - inter;
        if (inter * b_un > b_in * un) { b_in = inter; b_un = un; b_ix = g; }
    }
    size_t o = (size_t)b * PP + p;
    g_bt_ov[o] = b_in / b_un;
    g_bt_idx[o] = b_ix;
}

// ---------------- phase B: per-GT max/argmax over priors ----------------
__global__ void __launch_bounds__(256) k_phaseB(const float* __restrict__ priors,
                                                const float* __restrict__ targets) {
    int g = blockIdx.x, b = blockIdx.y;
    int tid = threadIdx.x;
    const float* t = targets + ((size_t)b * GG + g) * 15;
    float x1 = t[0], y1 = t[1], x2 = t[2], y2 = t[3];
    float tarea = (x2 - x1) * (y2 - y1);

    float b_in = -1.0f, b_un = 1.0f;
    int b_ix = 0;
    for (int p = tid; p < PP; p += blockDim.x) {
        float4 pr = ((const float4*)priors)[p];
        float px1 = pr.x - pr.z * 0.5f, py1 = pr.y - pr.w * 0.5f;
        float px2 = pr.x + pr.z * 0.5f, py2 = pr.y + pr.w * 0.5f;
        float parea = (px2 - px1) * (py2 - py1);
        float lx = fmaxf(x1, px1), ly = fmaxf(y1, py1);
        float rx = fminf(x2, px2), ry = fminf(y2, py2);
        float w = fmaxf(rx - lx, 0.0f), h = fmaxf(ry - ly, 0.0f);
        float inter = w * h;
        float un = tarea + parea - inter;
        if (inter * b_un > b_in * un) { b_in = inter; b_un = un; b_ix = p; }
    }

    __shared__ float si[256], su[256];
    __shared__ int sx[256];
    si[tid] = b_in; su[tid] = b_un; sx[tid] = b_ix;
    __syncthreads();
    for (int s = 128; s > 0; s >>= 1) {
        if (tid < s) {
            float ci = si[tid + s], cu = su[tid + s];
            int cx = sx[tid + s];
            float l = ci * su[tid], r = si[tid] * cu;
            if (l > r || (l == r && cx < sx[tid])) {
                si[tid] = ci; su[tid] = cu; sx[tid] = cx;
            }
        }
        __syncthreads();
    }
    if (tid == 0) {
        g_bp_ov[b * GG + g] = si[0] / su[0];
        g_bp_idx[b * GG + g] = sx[0];
    }
}

// ---------------- scatter corrections (sequential per batch; last-wins) ---
__global__ void __launch_bounds__(32) k_scatter() {
    int b = blockIdx.x;
    if (threadIdx.x != 0) return;
    int any = 0;
    float* ov = g_bt_ov + (size_t)b * PP;
    int* ix = g_bt_idx + (size_t)b * PP;
    for (int g = 0; g < GG; g++) {
        float bpo = g_bp_ov[b * GG + g];
        int bp = g_bp_idx[b * GG + g];
        if (bpo >= 0.2f) {
            any = 1;
            if (ov[bp] < 2.0f) ov[bp] = 2.0f;
        }
        ix[bp] = g;  // always set, matching reference (.set not masked by valid)
    }
    g_anyvalid[b] = any;
}

// ---------------- per-prior losses + loss_c buffer ----------------
__global__ void __launch_bounds__(256) k_losses(const float* __restrict__ loc_data,
                                                const float* __restrict__ conf_data,
                                                const float* __restrict__ landm_data,
                                                const float* __restrict__ priors,
                                                const float* __restrict__ targets) {
    int b = blockIdx.y;
    int p = blockIdx.x * blockDim.x + threadIdx.x;
    size_t o = (size_t)b * PP + p;
    float ov = g_bt_ov[o];
    int g = g_bt_idx[o];
    int av = g_anyvalid[b];

    int conf = 0;
    if (av && ov >= 0.35f)
        conf = (int)targets[((size_t)b * GG + g) * 15 + 14];

    const float* cd = conf_data + o * 3;
    float c0 = cd[0], c1 = cd[1], c2 = cd[2];
    float mx = fmaxf(c0, fmaxf(c1, c2));
    float lse = mx + logf(expf(c0 - mx) + expf(c1 - mx) + expf(c2 - mx));
    float gathered = (conf == 0) ? c0 : ((conf == 1) ? c1 : c2);
    float lcv = lse - gathered;
    int ispos = conf > 0;
    g_lossc[o] = ispos ? 0.0f : lcv;

    double d_l = 0.0, d_lm = 0.0, d_cp = 0.0;
    if (ispos) {
        d_cp = (double)lcv;
        const float* t = targets + ((size_t)b * GG + g) * 15;
        float4 pr = ((const float4*)priors)[p];
        float dwx = 0.1f * pr.z, dwy = 0.1f * pr.w;
        float m0 = t[0], m1 = t[1], m2 = t[2], m3 = t[3];
        float gcx = ((m0 + m2) * 0.5f - pr.x) / dwx;
        float gcy = ((m1 + m3) * 0.5f - pr.y) / dwy;
        float gw = logf((m2 - m0) / pr.z) / 0.2f;
        float gh = logf((m3 - m1) / pr.w) / 0.2f;
        const float* ld = loc_data + o * 4;
        d_l = (double)(sl1(ld[0] - gcx) + sl1(ld[1] - gcy) +
                       sl1(ld[2] - gw) + sl1(ld[3] - gh));
        const float* lt = t + 4;
        const float* lm = landm_data + o * 10;
        int nd = (conf == 1) ? 10 : 4;  // conf==2 -> first 4 dims only
        float s = 0.0f;
        for (int i = 0; i < nd; i += 2) {
            float lx = (lt[i] - pr.x) / dwx;
            float ly = (lt[i + 1] - pr.y) / dwy;
            s += sl1(lm[i] - lx) + sl1(lm[i + 1] - ly);
        }
        d_lm = (double)s;
    }

    // warp reduce (pos is sparse; only warps with pos touch atomics)
    int np = ispos;
    for (int off = 16; off > 0; off >>= 1) {
        d_l  += __shfl_down_sync(0xFFFFFFFFu, d_l, off);
        d_lm += __shfl_down_sync(0xFFFFFFFFu, d_lm, off);
        d_cp += __shfl_down_sync(0xFFFFFFFFu, d_cp, off);
        np   += __shfl_down_sync(0xFFFFFFFFu, np, off);
    }
    if ((threadIdx.x & 31) == 0 && np > 0) {
        atomicAdd(&g_accb[b][0], d_l);
        atomicAdd(&g_accb[b][1], d_lm);
        atomicAdd(&g_accb[b][2], d_cp);
        atomicAdd(&g_numpos[b], np);
    }
}

// ---------------- per-batch sum-of-top-k via ballot radix select ----------
// k = min(7*num_pos, P-1). Values are >= 0 so float bit order == value order.
#define TKT 512
__global__ void __launch_bounds__(TKT) k_topk() {
    int b = blockIdx.x;
    int np = g_numpos[b];
    long long kk = 7LL * np;
    if (kk > PP - 1) kk = PP - 1;
    if (kk <= 0) return;
    int k = (int)kk;

    const float* v = g_lossc + (size_t)b * PP;
    int tid = threadIdx.x;
    int lane = tid & 31, wid = tid >> 5;   // 16 warps

    __shared__ int swh[TKT / 32][16];
    __shared__ unsigned s_prefix;
    __shared__ int s_krem;

    unsigned prefix = 0;
    int krem = k;
    for (int shift = 28; shift >= 0; shift -= 4) {
        unsigned hmask = (shift == 28) ? 0u : (0xFFFFFFFFu << (shift + 4));
        int acc = 0;  // lane j<16 owns bin j
        for (int i = tid; i < PP; i += TKT) {
            unsigned u = __float_as_uint(v[i]);
            bool valid = ((u & hmask) == prefix);
            unsigned d = (u >> shift) & 15u;
            unsigned bv = __ballot_sync(0xFFFFFFFFu, valid);
            unsigned b0 = __ballot_sync(0xFFFFFFFFu, (d & 1u) != 0u);
            unsigned b1 = __ballot_sync(0xFFFFFFFFu, (d & 2u) != 0u);
            unsigned b2 = __ballot_sync(0xFFFFFFFFu, (d & 4u) != 0u);
            unsigned b3 = __ballot_sync(0xFFFFFFFFu, (d & 8u) != 0u);
            if (lane < 16) {
                unsigned m = bv;
                m &= (lane & 1) ? b0 : ~b0;
                m &= (lane & 2) ? b1 : ~b1;
                m &= (lane & 4) ? b2 : ~b2;
                m &= (lane & 8) ? b3 : ~b3;
                acc += __popc(m);
            }
        }
        if (lane < 16) swh[wid][lane] = acc;
        __syncthreads();
        if (tid == 0) {
            int hist[16];
            for (int j = 0; j < 16; j++) {
                int s = 0;
                for (int w = 0; w < TKT / 32; w++) s += swh[w][j];
                hist[j] = s;
            }
            int a = 0, bin = 15;
            for (; bin > 0; bin--) {
                if (a + hist[bin] >= krem) break;
                a += hist[bin];
            }
            s_prefix = prefix | ((unsigned)bin << shift);
            s_krem = krem - a;
        }
        __syncthreads();
        prefix = s_prefix;
        krem = s_krem;
        __syncthreads();
    }

    // prefix = bit pattern of the k-th largest value
    float t = __uint_as_float(prefix);
    double s = 0.0;
    int c = 0;
    for (int i = tid; i < PP; i += TKT) {
        float x = v[i];
        if (x > t) { s += (double)x; c++; }
    }
    for (int off = 16; off > 0; off >>= 1) {
        s += __shfl_down_sync(0xFFFFFFFFu, s, off);
        c += __shfl_down_sync(0xFFFFFFFFu, c, off);
    }
    __shared__ double sd[TKT / 32];
    __shared__ int sc[TKT / 32];
    if (lane == 0) { sd[wid] = s; sc[wid] = c; }
    __syncthreads();
    if (tid == 0) {
        double S = 0.0;
        int C = 0;
        for (int w = 0; w < TKT / 32; w++) { S += sd[w]; C += sc[w]; }
        double res = S + (double)(k - C) * (double)t;
        atomicAdd(&g_topk, res);
    }
}

// ---------------- finalize ----------------
__global__ void __launch_bounds__(32) k_final(float* out) {
    if (threadIdx.x != 0) return;
    double ll = 0.0, lm = 0.0, lc = 0.0;
    int tp = 0;
    for (int b = 0; b < BB; b++) {
        ll += g_accb[b][0];
        lm += g_accb[b][1];
        lc += g_accb[b][2];
        tp += g_numpos[b];
    }
    double N = tp > 0 ? (double)tp : 1.0;  // N == N1 here (conf >= 0 always)
    out[0] = (float)(ll / N);
    out[1] = (float)((lc + g_topk) / N);
    out[2] = (float)(lm / N);
}

// ---------------- launch ----------------
extern "C" void kernel_launch(void* const* d_in, const int* in_sizes, int n_in,
                              void* d_out, int out_size) {
    const float *loc = nullptr, *conf = nullptr, *landm = nullptr;
    const float *priors = nullptr, *targets = nullptr;
    for (int i = 0; i < n_in; i++) {
        long long s = in_sizes[i];
        if (s == (long long)BB * PP * 4)       loc     = (const float*)d_in[i];
        else if (s == (long long)BB * PP * 3)  conf    = (const float*)d_in[i];
        else if (s == (long long)BB * PP * 10) landm   = (const float*)d_in[i];
        else if (s == (long long)PP * 4)       priors  = (const float*)d_in[i];
        else if (s == (long long)BB * GG * 15) targets = (const float*)d_in[i];
    }

    k_init<<<1, 64>>>();
    dim3 gA(PP / 256, BB);
    k_phaseA<<<gA, 256>>>(priors, targets);
    dim3 gB(GG, BB);
    k_phaseB<<<gB, 256>>>(priors, targets);
    k_scatter<<<BB, 32>>>();
    k_losses<<<gA, 256>>>(loc, conf, landm, priors, targets);
    k_topk<<<BB, TKT>>>();
    k_final<<<1, 32>>>((float*)d_out);
}